// round 6
// baseline (speedup 1.0000x reference)
#include <cuda_runtime.h>
#include <cuda_bf16.h>

// Problem constants
#define NRAYS   8192
#define KG      4096
#define GSZ     32                     // rays per group (one warp)
#define NGROUP  (NRAYS / GSZ)          // 256 groups
#define GRIDY   8                      // gaussian splits (512 each)
#define KSLICE  (KG / GRIDY)           // 512
#define QCUT    24.0f                  // skip if q >= QCUT (err <= 4096*2^-24 = 2.4e-4 logit)

// s = sqrt(0.5 * log2(e)) : folds exp(-0.5 q) -> 2^(-||W d||^2)
#define SCALE_S 0.8493281132464818f

#define SORT_BLOCKS 16                 // 512 rays per sort block

// ---- scratch (__device__ globals; no allocations) -------------------------
__device__ __align__(16) float  g_coef[KG * 16];      // W(10), nc(4), lab, pad
__device__ __align__(16) float  g_abs [KG * 12];      // |W|(10), pad(2)
__device__ __align__(16) float4 g_rays[NRAYS];        // sorted rays
__device__ int      g_perm[NRAYS];                    // sorted slot -> original n
__device__ int      g_key [NRAYS];                    // 8-bit morton key per ray
__device__ int      g_lrank[NRAYS];                   // stable rank within sort block
__device__ unsigned g_bhist[SORT_BLOCKS * 256];       // block hist -> block base
__device__ unsigned g_keybase[256];                   // global key base
__device__ float    g_partial[NRAYS * GRIDY];         // 256 KB

__device__ __forceinline__ float ex2f(float x) {
    float e;
    asm("ex2.approx.ftz.f32 %0, %1;" : "=f"(e) : "f"(x));
    return e;
}

// ---------------------------------------------------------------------------
// Kernel 1: gaussian setup. 32 blocks x 128 threads.
// ---------------------------------------------------------------------------
__global__ void __launch_bounds__(128)
setup_kernel(const float* __restrict__ emb,
             const float* __restrict__ chol,
             const float* __restrict__ labels,
             const int*   __restrict__ idx)
{
    int k = blockIdx.x * 128 + threadIdx.x;
    int m = __ldg(idx + k);
    const float4* c4 = reinterpret_cast<const float4*>(chol) + (size_t)m * 4;
    float4 r0 = c4[0], r1 = c4[1], r2 = c4[2], r3 = c4[3];
    float L00 = r0.x;
    float L10 = r1.x, L11 = r1.y;
    float L20 = r2.x, L21 = r2.y, L22 = r2.z;
    float L30 = r3.x, L31 = r3.y, L32 = r3.z, L33 = r3.w;

    float i0 = 1.0f / L00, i1 = 1.0f / L11, i2 = 1.0f / L22, i3 = 1.0f / L33;

    float U00 = i0, U11 = i1, U22 = i2, U33 = i3;
    float U10 = -(L10 * U00) * i1;
    float U20 = -(L20 * U00 + L21 * U10) * i2;
    float U21 = -(L21 * U11) * i2;
    float U30 = -(L30 * U00 + L31 * U10 + L32 * U20) * i3;
    float U31 = -(L31 * U11 + L32 * U21) * i3;
    float U32 = -(L32 * U22) * i3;

    const float s = SCALE_S;
    U00 *= s; U10 *= s; U11 *= s; U20 *= s; U21 *= s; U22 *= s;
    U30 *= s; U31 *= s; U32 *= s; U33 *= s;

    float4 mu = reinterpret_cast<const float4*>(emb)[m];
    float nc0 = -(U00 * mu.x);
    float nc1 = -(U10 * mu.x + U11 * mu.y);
    float nc2 = -(U20 * mu.x + U21 * mu.y + U22 * mu.z);
    float nc3 = -(U30 * mu.x + U31 * mu.y + U32 * mu.z + U33 * mu.w);
    float lab = __ldg(labels + m);

    float4* co = reinterpret_cast<float4*>(g_coef + (size_t)k * 16);
    co[0] = make_float4(U00, U10, U11, U20);
    co[1] = make_float4(U21, U22, U30, U31);
    co[2] = make_float4(U32, U33, nc0, nc1);
    co[3] = make_float4(nc2, nc3, lab, 0.0f);

    float4* ao = reinterpret_cast<float4*>(g_abs + (size_t)k * 12);
    ao[0] = make_float4(fabsf(U00), fabsf(U10), fabsf(U11), fabsf(U20));
    ao[1] = make_float4(fabsf(U21), fabsf(U22), fabsf(U30), fabsf(U31));
    ao[2] = make_float4(fabsf(U32), fabsf(U33), 0.0f, 0.0f);
}

// ---------------------------------------------------------------------------
// Kernel 2a: sort histogram + stable local rank. 16 blocks x 512 threads.
// ---------------------------------------------------------------------------
__global__ void __launch_bounds__(512)
sort_hist_kernel(const float* __restrict__ org,
                 const float* __restrict__ dir)
{
    __shared__ unsigned whist[16][256];

    const int tid  = threadIdx.x;
    const int lane = tid & 31;
    const int w    = tid >> 5;
    const int n    = blockIdx.x * 512 + tid;

    for (int i = tid; i < 16 * 256; i += 512)
        (&whist[0][0])[i] = 0u;
    __syncthreads();

    float2 o = reinterpret_cast<const float2*>(org)[n];
    float2 d = reinterpret_cast<const float2*>(dir)[n];
    int bx = min(3, max(0, (int)(o.x * 4.0f)));
    int by = min(3, max(0, (int)(o.y * 4.0f)));
    int cx = min(3, max(0, (int)(d.x * 4.0f)));
    int cy = min(3, max(0, (int)(d.y * 4.0f)));
    int key = ((bx >> 1) << 7) | ((by >> 1) << 6) | ((cx >> 1) << 5) | ((cy >> 1) << 4)
            | ((bx & 1) << 3) | ((by & 1) << 2) | ((cx & 1) << 1) | (cy & 1);

    unsigned mask = __match_any_sync(0xFFFFFFFFu, key);
    unsigned lt   = mask & ((1u << lane) - 1u);
    int wrank = __popc(lt);
    if (lt == 0u)                       // leader
        whist[w][key] = (unsigned)__popc(mask);
    __syncthreads();

    // stable rank within block: sum of earlier warps' counts for this key
    unsigned r = (unsigned)wrank;
    for (int ww = 0; ww < 16; ww++) {
        unsigned c = whist[ww][key];
        if (ww < w) r += c;
    }
    g_key[n]   = key;
    g_lrank[n] = (int)r;

    // block histogram
    if (tid < 256) {
        unsigned bh = 0;
#pragma unroll
        for (int ww = 0; ww < 16; ww++) bh += whist[ww][tid];
        g_bhist[blockIdx.x * 256 + tid] = bh;
    }
}

// ---------------------------------------------------------------------------
// Kernel 2b: scan. 1 block x 256 threads (thread = key).
// ---------------------------------------------------------------------------
__global__ void __launch_bounds__(256)
sort_scan_kernel()
{
    __shared__ unsigned totals[256];
    const int key  = threadIdx.x;
    const int lane = key & 31;

    unsigned off = 0;
#pragma unroll
    for (int b = 0; b < SORT_BLOCKS; b++) {
        unsigned c = g_bhist[b * 256 + key];
        g_bhist[b * 256 + key] = off;
        off += c;
    }
    totals[key] = off;
    __syncthreads();

    if (key < 32) {
        unsigned v[8], loc = 0;
#pragma unroll
        for (int i = 0; i < 8; i++) { v[i] = totals[key * 8 + i]; loc += v[i]; }
        unsigned inc = loc;
#pragma unroll
        for (int ofs = 1; ofs < 32; ofs <<= 1) {
            unsigned t = __shfl_up_sync(0xFFFFFFFFu, inc, ofs);
            if (lane >= ofs) inc += t;
        }
        unsigned run = inc - loc;
#pragma unroll
        for (int i = 0; i < 8; i++) { g_keybase[key * 8 + i] = run; run += v[i]; }
    }
}

// ---------------------------------------------------------------------------
// Kernel 2c: scatter. 16 blocks x 512 threads.
// ---------------------------------------------------------------------------
__global__ void __launch_bounds__(512)
sort_scatter_kernel(const float* __restrict__ org,
                    const float* __restrict__ dir)
{
    const int n   = blockIdx.x * 512 + threadIdx.x;
    const int key = g_key[n];
    int pos = (int)(g_keybase[key] + g_bhist[blockIdx.x * 256 + key]) + g_lrank[n];
    float2 o = reinterpret_cast<const float2*>(org)[n];
    float2 d = reinterpret_cast<const float2*>(dir)[n];
    g_rays[pos] = make_float4(o.x, o.y, d.x, d.y);
    g_perm[pos] = n;
}

// ---------------------------------------------------------------------------
// Kernel 3: eval. grid (NGROUP/4, GRIDY), block 128 (4 warps, warp = group).
// Per warp: 32 rays (1/lane), bbox via shfl, tile-wise cull of 512 gaussians,
// survivor compaction to shared, eval with warp-coherent early exit.
// ---------------------------------------------------------------------------
__global__ void __launch_bounds__(128)
eval_kernel(float* __restrict__ partial)
{
    __shared__ float4 sbuf[4][GSZ * 4];    // 8 KB survivor coeffs per warp

    const int tid  = threadIdx.x;
    const int lane = tid & 31;
    const int w    = tid >> 5;
    const int grp  = blockIdx.x * 4 + w;
    const int slot = grp * GSZ + lane;

    float4 ray = g_rays[slot];
    float acc = 0.0f;

    // per-warp bbox
    float lx = ray.x, hx = ray.x, ly = ray.y, hy = ray.y;
    float lz = ray.z, hz = ray.z, lw = ray.w, hw = ray.w;
#pragma unroll
    for (int ofs = 16; ofs > 0; ofs >>= 1) {
        lx = fminf(lx, __shfl_xor_sync(0xFFFFFFFFu, lx, ofs));
        hx = fmaxf(hx, __shfl_xor_sync(0xFFFFFFFFu, hx, ofs));
        ly = fminf(ly, __shfl_xor_sync(0xFFFFFFFFu, ly, ofs));
        hy = fmaxf(hy, __shfl_xor_sync(0xFFFFFFFFu, hy, ofs));
        lz = fminf(lz, __shfl_xor_sync(0xFFFFFFFFu, lz, ofs));
        hz = fmaxf(hz, __shfl_xor_sync(0xFFFFFFFFu, hz, ofs));
        lw = fminf(lw, __shfl_xor_sync(0xFFFFFFFFu, lw, ofs));
        hw = fmaxf(hw, __shfl_xor_sync(0xFFFFFFFFu, hw, ofs));
    }
    float4 c = make_float4(0.5f * (lx + hx), 0.5f * (ly + hy),
                           0.5f * (lz + hz), 0.5f * (lw + hw));
    float4 r = make_float4(0.5f * (hx - lx) + 1e-6f, 0.5f * (hy - ly) + 1e-6f,
                           0.5f * (hz - lz) + 1e-6f, 0.5f * (hw - lw) + 1e-6f);

    const int kbase = blockIdx.y * KSLICE;
    float4* mybuf = sbuf[w];

    for (int t = 0; t < KSLICE / 32; t++) {
        int k = kbase + t * 32 + lane;
        const float4* cf = reinterpret_cast<const float4*>(g_coef + (size_t)k * 16);
        float4 f0 = cf[0], f1 = cf[1], f2 = cf[2], f3 = cf[3];
        const float4* af = reinterpret_cast<const float4*>(g_abs + (size_t)k * 12);
        float4 b0 = af[0], b1 = af[1], b2 = af[2];

        // interval bound on y over bbox
        float yc0 = __fmaf_rn(f0.x, c.x, f2.z);
        float rh0 = b0.x * r.x;
        float yc1 = __fmaf_rn(f0.y, c.x, f2.w); yc1 = __fmaf_rn(f0.z, c.y, yc1);
        float rh1 = __fmaf_rn(b0.z, r.y, b0.y * r.x);
        float yc2 = __fmaf_rn(f0.w, c.x, f3.x); yc2 = __fmaf_rn(f1.x, c.y, yc2);
        yc2 = __fmaf_rn(f1.y, c.z, yc2);
        float rh2 = __fmaf_rn(b1.y, r.z, __fmaf_rn(b1.x, r.y, b0.w * r.x));
        float yc3 = __fmaf_rn(f1.z, c.x, f3.y); yc3 = __fmaf_rn(f1.w, c.y, yc3);
        yc3 = __fmaf_rn(f2.x, c.z, yc3); yc3 = __fmaf_rn(f2.y, c.w, yc3);
        float rh3 = __fmaf_rn(b2.y, r.w, __fmaf_rn(b2.x, r.z,
                    __fmaf_rn(b1.w, r.y, b1.z * r.x)));

        float m0 = fmaxf(fabsf(yc0) - rh0, 0.0f);
        float m1 = fmaxf(fabsf(yc1) - rh1, 0.0f);
        float m2 = fmaxf(fabsf(yc2) - rh2, 0.0f);
        float m3 = fmaxf(fabsf(yc3) - rh3, 0.0f);
        float qmin = __fmaf_rn(m0, m0, __fmaf_rn(m1, m1,
                     __fmaf_rn(m2, m2, m3 * m3)));

        bool sv = qmin < QCUT;
        unsigned mask = __ballot_sync(0xFFFFFFFFu, sv);
        int nsurv = __popc(mask);
        if (sv) {
            int s = __popc(mask & ((1u << lane) - 1u));
            float4* dst = mybuf + s * 4;
            dst[0] = f0; dst[1] = f1; dst[2] = f2; dst[3] = f3;
        }
        __syncwarp();

        for (int i = 0; i < nsurv; i++) {
            const float4* sp = mybuf + i * 4;
            float4 s0 = sp[0], s1 = sp[1], s2 = sp[2], s3 = sp[3];

            float y0 = __fmaf_rn(s0.x, ray.x, s2.z);
            float y1 = __fmaf_rn(s0.y, ray.x, s2.w);
            y1 = __fmaf_rn(s0.z, ray.y, y1);
            float q01 = __fmaf_rn(y1, y1, y0 * y0);

            // warp-coherent early exit on the well-sorted dims
            if (__ballot_sync(0xFFFFFFFFu, q01 < QCUT)) {
                float y2 = __fmaf_rn(s0.w, ray.x, s3.x);
                y2 = __fmaf_rn(s1.x, ray.y, y2);
                y2 = __fmaf_rn(s1.y, ray.z, y2);
                float y3 = __fmaf_rn(s1.z, ray.x, s3.y);
                y3 = __fmaf_rn(s1.w, ray.y, y3);
                y3 = __fmaf_rn(s2.x, ray.z, y3);
                y3 = __fmaf_rn(s2.y, ray.w, y3);
                float q = __fmaf_rn(y2, y2, q01);
                q = __fmaf_rn(y3, y3, q);
                if (q < QCUT)
                    acc = __fmaf_rn(s3.z, ex2f(-q), acc);
            }
        }
        __syncwarp();
    }

    partial[(size_t)slot * GRIDY + blockIdx.y] = acc;
}

// ---------------------------------------------------------------------------
// Kernel 4: reduce GRIDY partials per sorted slot, sigmoid, scatter via perm.
// ---------------------------------------------------------------------------
__global__ void __launch_bounds__(256)
reduce_kernel(const float* __restrict__ partial, float* __restrict__ out)
{
    int slot = blockIdx.x * 256 + threadIdx.x;
    const float4* p = reinterpret_cast<const float4*>(partial + (size_t)slot * GRIDY);
    float4 v0 = p[0], v1 = p[1];
    float s = ((v0.x + v0.y) + (v0.z + v0.w)) + ((v1.x + v1.y) + (v1.z + v1.w));
    float e = ex2f(-s * 1.4426950408889634f);
    out[g_perm[slot]] = 1.0f / (1.0f + e);
}

// ---------------------------------------------------------------------------
extern "C" void kernel_launch(void* const* d_in, const int* in_sizes, int n_in,
                              void* d_out, int out_size)
{
    const float* origins    = (const float*)d_in[0];
    const float* directions = (const float*)d_in[1];
    const float* embeddings = (const float*)d_in[2];
    const float* chol       = (const float*)d_in[3];
    const float* labels     = (const float*)d_in[4];
    const int*   idx        = (const int*)  d_in[5];
    float* out = (float*)d_out;

    float* part_ptr = nullptr;
    cudaGetSymbolAddress((void**)&part_ptr, g_partial);

    setup_kernel<<<KG / 128, 128>>>(embeddings, chol, labels, idx);
    sort_hist_kernel<<<SORT_BLOCKS, 512>>>(origins, directions);
    sort_scan_kernel<<<1, 256>>>();
    sort_scatter_kernel<<<SORT_BLOCKS, 512>>>(origins, directions);
    eval_kernel<<<dim3(NGROUP / 4, GRIDY), 128>>>(part_ptr);
    reduce_kernel<<<NRAYS / 256, 256>>>(part_ptr, out);
}

// round 7
// speedup vs baseline: 1.9518x; 1.9518x over previous
#include <cuda_runtime.h>
#include <cuda_bf16.h>

// Problem constants
#define NRAYS   8192
#define KSEL    4096
#define KSPLIT  64
#define CHUNK   (KSEL / KSPLIT)        // 64 gaussians per block
#define TPB     256
#define NPT     4                      // rays per thread
#define NBLK    (NRAYS / (TPB * NPT))  // 8 n-tile blocks

// Scratch (no allocations allowed): partial[n][KSPLIT] for contiguous reduce
__device__ float g_partial[NRAYS * KSPLIT];   // 2 MB

// s = sqrt(0.5 * log2(e)) : folds exp(-0.5 q) -> 2^(-||W d||^2)
#define SCALE_S 0.8493281132464818f

__device__ __forceinline__ float ex2f(float x) {
    float e;
    asm("ex2.approx.ftz.f32 %0, %1;" : "=f"(e) : "f"(x));
    return e;
}

// ---------------------------------------------------------------------------
// Fused kernel: grid (NBLK, KSPLIT), 256 threads.
// Phase 1 (threads 0..63): gather gaussian kbase+tid, compute W = s*L^{-1},
//   nc = -(W*mu), store [W(10), nc(4), lab, pad] to shared (float4 x4).
// Phase 2 (all): scalar FMA mainloop, 4 rays/thread over 64 gaussians.
// ---------------------------------------------------------------------------
__global__ void __launch_bounds__(TPB)
fused_kernel(const float* __restrict__ org,
             const float* __restrict__ dir,
             const float* __restrict__ emb,
             const float* __restrict__ chol,
             const float* __restrict__ labels,
             const int*   __restrict__ idx,
             float* __restrict__ partial)
{
    __shared__ float4 sm[CHUNK * 4];   // 4 KB

    const int tid   = threadIdx.x;
    const int nbase = blockIdx.x * (TPB * NPT);
    const int kbase = blockIdx.y * CHUNK;

    // ---- Phase 1: per-gaussian setup (threads 0..63) ----
    if (tid < CHUNK) {
        int m = __ldg(idx + kbase + tid);
        const float4* c4 = reinterpret_cast<const float4*>(chol) + (size_t)m * 4;
        float4 r0 = c4[0], r1 = c4[1], r2 = c4[2], r3 = c4[3];
        float L00 = r0.x;
        float L10 = r1.x, L11 = r1.y;
        float L20 = r2.x, L21 = r2.y, L22 = r2.z;
        float L30 = r3.x, L31 = r3.y, L32 = r3.z, L33 = r3.w;

        float i0 = 1.0f / L00, i1 = 1.0f / L11, i2 = 1.0f / L22, i3 = 1.0f / L33;

        float U00 = i0, U11 = i1, U22 = i2, U33 = i3;
        float U10 = -(L10 * U00) * i1;
        float U20 = -(L20 * U00 + L21 * U10) * i2;
        float U21 = -(L21 * U11) * i2;
        float U30 = -(L30 * U00 + L31 * U10 + L32 * U20) * i3;
        float U31 = -(L31 * U11 + L32 * U21) * i3;
        float U32 = -(L32 * U22) * i3;

        const float s = SCALE_S;
        U00 *= s; U10 *= s; U11 *= s; U20 *= s; U21 *= s; U22 *= s;
        U30 *= s; U31 *= s; U32 *= s; U33 *= s;

        float4 mu = reinterpret_cast<const float4*>(emb)[m];
        float nc0 = -(U00 * mu.x);
        float nc1 = -(U10 * mu.x + U11 * mu.y);
        float nc2 = -(U20 * mu.x + U21 * mu.y + U22 * mu.z);
        float nc3 = -(U30 * mu.x + U31 * mu.y + U32 * mu.z + U33 * mu.w);
        float lab = __ldg(labels + m);

        sm[tid * 4 + 0] = make_float4(U00, U10, U11, U20);
        sm[tid * 4 + 1] = make_float4(U21, U22, U30, U31);
        sm[tid * 4 + 2] = make_float4(U32, U33, nc0, nc1);
        sm[tid * 4 + 3] = make_float4(nc2, nc3, lab, 0.0f);
    }

    // ---- load rays (independent of shared) ----
    float p0[NPT], p1[NPT], p2[NPT], p3[NPT], acc[NPT];
    const float2* o2 = reinterpret_cast<const float2*>(org);
    const float2* d2 = reinterpret_cast<const float2*>(dir);
#pragma unroll
    for (int j = 0; j < NPT; j++) {
        int n = nbase + tid + j * TPB;
        float2 o = o2[n];
        float2 d = d2[n];
        p0[j] = o.x; p1[j] = o.y; p2[j] = d.x; p3[j] = d.y;
        acc[j] = 0.0f;
    }
    __syncthreads();

    // ---- Phase 2: scalar FMA mainloop ----
#pragma unroll 4
    for (int kk = 0; kk < CHUNK; kk++) {
        float4 f0 = sm[kk * 4 + 0];   // U00 U10 U11 U20
        float4 f1 = sm[kk * 4 + 1];   // U21 U22 U30 U31
        float4 f2 = sm[kk * 4 + 2];   // U32 U33 nc0 nc1
        float4 f3 = sm[kk * 4 + 3];   // nc2 nc3 lab pad
#pragma unroll
        for (int j = 0; j < NPT; j++) {
            float y0 = __fmaf_rn(f0.x, p0[j], f2.z);
            float y1 = __fmaf_rn(f0.y, p0[j], f2.w);
            y1 = __fmaf_rn(f0.z, p1[j], y1);
            float y2 = __fmaf_rn(f0.w, p0[j], f3.x);
            y2 = __fmaf_rn(f1.x, p1[j], y2);
            y2 = __fmaf_rn(f1.y, p2[j], y2);
            float y3 = __fmaf_rn(f1.z, p0[j], f3.y);
            y3 = __fmaf_rn(f1.w, p1[j], y3);
            y3 = __fmaf_rn(f2.x, p2[j], y3);
            y3 = __fmaf_rn(f2.y, p3[j], y3);
            // negated squared norm (negation folds into FFMA operand)
            float qn = -(y0 * y0);
            qn = __fmaf_rn(y1, -y1, qn);
            qn = __fmaf_rn(y2, -y2, qn);
            qn = __fmaf_rn(y3, -y3, qn);
            acc[j] = __fmaf_rn(f3.z, ex2f(qn), acc[j]);
        }
    }

    // ---- write partial[n][ky] (contiguous-per-n layout for fast reduce) ----
    const int ky = blockIdx.y;
#pragma unroll
    for (int j = 0; j < NPT; j++) {
        int n = nbase + tid + j * TPB;
        partial[(size_t)n * KSPLIT + ky] = acc[j];
    }
}

// ---------------------------------------------------------------------------
// Reduce: 64 contiguous floats per ray (16x float4, MLP-friendly) + sigmoid.
// ---------------------------------------------------------------------------
__global__ void __launch_bounds__(256)
reduce_kernel(const float* __restrict__ partial, float* __restrict__ out)
{
    int n = blockIdx.x * 256 + threadIdx.x;
    const float4* p = reinterpret_cast<const float4*>(partial + (size_t)n * KSPLIT);
    float s0 = 0.0f, s1 = 0.0f, s2 = 0.0f, s3 = 0.0f;
#pragma unroll
    for (int i = 0; i < KSPLIT / 16; i++) {
        float4 v0 = p[i * 4 + 0];
        float4 v1 = p[i * 4 + 1];
        float4 v2 = p[i * 4 + 2];
        float4 v3 = p[i * 4 + 3];
        s0 += (v0.x + v0.y) + (v0.z + v0.w);
        s1 += (v1.x + v1.y) + (v1.z + v1.w);
        s2 += (v2.x + v2.y) + (v2.z + v2.w);
        s3 += (v3.x + v3.y) + (v3.z + v3.w);
    }
    float s = (s0 + s1) + (s2 + s3);
    float e = ex2f(-s * 1.4426950408889634f);
    out[n] = 1.0f / (1.0f + e);
}

// ---------------------------------------------------------------------------
extern "C" void kernel_launch(void* const* d_in, const int* in_sizes, int n_in,
                              void* d_out, int out_size)
{
    const float* origins    = (const float*)d_in[0];
    const float* directions = (const float*)d_in[1];
    const float* embeddings = (const float*)d_in[2];
    const float* chol       = (const float*)d_in[3];
    const float* labels     = (const float*)d_in[4];
    const int*   idx        = (const int*)  d_in[5];
    float* out = (float*)d_out;

    float* part_ptr = nullptr;
    cudaGetSymbolAddress((void**)&part_ptr, g_partial);

    fused_kernel<<<dim3(NBLK, KSPLIT), TPB>>>(origins, directions, embeddings,
                                              chol, labels, idx, part_ptr);
    reduce_kernel<<<NRAYS / 256, 256>>>(part_ptr, out);
}

// round 8
// speedup vs baseline: 1.9837x; 1.0163x over previous
#include <cuda_runtime.h>
#include <cuda_bf16.h>

// Problem constants
#define NRAYS   8192
#define KSEL    4096
#define KSPLIT  64
#define CHUNK   (KSEL / KSPLIT)        // 64 gaussians per block
#define TPB     256
#define NPT     2                      // rays per thread
#define RPB     (TPB * NPT)            // 512 rays per block column
#define NBLK    (NRAYS / RPB)          // 16 n-tile columns -> grid (16,64)=1024 blocks

// s = sqrt(0.5 * log2(e)) : folds exp(-0.5 q) -> 2^(-||W d||^2)
#define SCALE_S 0.8493281132464818f
#define FIXSCALE 1073741824.0          // 2^30 fixed-point scale (double)
#define INVFIX   (1.0f / 1073741824.0f)

// ---- scratch (__device__ globals; zero-initialized, self-resetting) -------
__device__ unsigned long long g_acc[NRAYS];   // fixed-point logit accumulators
__device__ unsigned           g_cnt[NBLK];    // per-column completion tickets

__device__ __forceinline__ float ex2f(float x) {
    float e;
    asm("ex2.approx.ftz.f32 %0, %1;" : "=f"(e) : "f"(x));
    return e;
}

// ---------------------------------------------------------------------------
// Single fused kernel: grid (NBLK, KSPLIT), 256 threads.
//  Phase 1 (threads 0..63): gather gaussian kbase+tid, W = s*L^{-1},
//    nc = -(W*mu), stage [W(10), nc(4), lab, pad] in shared.
//  Phase 2: scalar FMA mainloop, NPT rays/thread over CHUNK gaussians.
//  Phase 3: deterministic integer fixed-point atomic combine; the last
//    block of each ray column applies sigmoid, writes out, resets state.
// ---------------------------------------------------------------------------
__global__ void __launch_bounds__(TPB)
fused_kernel(const float* __restrict__ org,
             const float* __restrict__ dir,
             const float* __restrict__ emb,
             const float* __restrict__ chol,
             const float* __restrict__ labels,
             const int*   __restrict__ idx,
             float* __restrict__ out)
{
    __shared__ float4 sm[CHUNK * 4];   // 4 KB
    __shared__ int s_last;

    const int tid   = threadIdx.x;
    const int nbase = blockIdx.x * RPB;
    const int kbase = blockIdx.y * CHUNK;

    // ---- Phase 1: per-gaussian setup (threads 0..63) ----
    if (tid < CHUNK) {
        int m = __ldg(idx + kbase + tid);
        const float4* c4 = reinterpret_cast<const float4*>(chol) + (size_t)m * 4;
        float4 r0 = c4[0], r1 = c4[1], r2 = c4[2], r3 = c4[3];
        float L00 = r0.x;
        float L10 = r1.x, L11 = r1.y;
        float L20 = r2.x, L21 = r2.y, L22 = r2.z;
        float L30 = r3.x, L31 = r3.y, L32 = r3.z, L33 = r3.w;

        float i0 = 1.0f / L00, i1 = 1.0f / L11, i2 = 1.0f / L22, i3 = 1.0f / L33;

        float U00 = i0, U11 = i1, U22 = i2, U33 = i3;
        float U10 = -(L10 * U00) * i1;
        float U20 = -(L20 * U00 + L21 * U10) * i2;
        float U21 = -(L21 * U11) * i2;
        float U30 = -(L30 * U00 + L31 * U10 + L32 * U20) * i3;
        float U31 = -(L31 * U11 + L32 * U21) * i3;
        float U32 = -(L32 * U22) * i3;

        const float s = SCALE_S;
        U00 *= s; U10 *= s; U11 *= s; U20 *= s; U21 *= s; U22 *= s;
        U30 *= s; U31 *= s; U32 *= s; U33 *= s;

        float4 mu = reinterpret_cast<const float4*>(emb)[m];
        float nc0 = -(U00 * mu.x);
        float nc1 = -(U10 * mu.x + U11 * mu.y);
        float nc2 = -(U20 * mu.x + U21 * mu.y + U22 * mu.z);
        float nc3 = -(U30 * mu.x + U31 * mu.y + U32 * mu.z + U33 * mu.w);
        float lab = __ldg(labels + m);

        sm[tid * 4 + 0] = make_float4(U00, U10, U11, U20);
        sm[tid * 4 + 1] = make_float4(U21, U22, U30, U31);
        sm[tid * 4 + 2] = make_float4(U32, U33, nc0, nc1);
        sm[tid * 4 + 3] = make_float4(nc2, nc3, lab, 0.0f);
    }

    // ---- load rays (independent of shared) ----
    float p0[NPT], p1[NPT], p2[NPT], p3[NPT], acc[NPT];
    const float2* o2 = reinterpret_cast<const float2*>(org);
    const float2* d2 = reinterpret_cast<const float2*>(dir);
#pragma unroll
    for (int j = 0; j < NPT; j++) {
        int n = nbase + tid + j * TPB;
        float2 o = o2[n];
        float2 d = d2[n];
        p0[j] = o.x; p1[j] = o.y; p2[j] = d.x; p3[j] = d.y;
        acc[j] = 0.0f;
    }
    __syncthreads();

    // ---- Phase 2: scalar FMA mainloop ----
#pragma unroll 4
    for (int kk = 0; kk < CHUNK; kk++) {
        float4 f0 = sm[kk * 4 + 0];   // U00 U10 U11 U20
        float4 f1 = sm[kk * 4 + 1];   // U21 U22 U30 U31
        float4 f2 = sm[kk * 4 + 2];   // U32 U33 nc0 nc1
        float4 f3 = sm[kk * 4 + 3];   // nc2 nc3 lab pad
#pragma unroll
        for (int j = 0; j < NPT; j++) {
            float y0 = __fmaf_rn(f0.x, p0[j], f2.z);
            float y1 = __fmaf_rn(f0.y, p0[j], f2.w);
            y1 = __fmaf_rn(f0.z, p1[j], y1);
            float y2 = __fmaf_rn(f0.w, p0[j], f3.x);
            y2 = __fmaf_rn(f1.x, p1[j], y2);
            y2 = __fmaf_rn(f1.y, p2[j], y2);
            float y3 = __fmaf_rn(f1.z, p0[j], f3.y);
            y3 = __fmaf_rn(f1.w, p1[j], y3);
            y3 = __fmaf_rn(f2.x, p2[j], y3);
            y3 = __fmaf_rn(f2.y, p3[j], y3);
            float qn = -(y0 * y0);
            qn = __fmaf_rn(y1, -y1, qn);
            qn = __fmaf_rn(y2, -y2, qn);
            qn = __fmaf_rn(y3, -y3, qn);
            acc[j] = __fmaf_rn(f3.z, ex2f(qn), acc[j]);
        }
    }

    // ---- Phase 3: deterministic integer combine ----
#pragma unroll
    for (int j = 0; j < NPT; j++) {
        int n = nbase + tid + j * TPB;
        long long v = (long long)((double)acc[j] * FIXSCALE);  // exact-ish, order-free sum
        atomicAdd(&g_acc[n], (unsigned long long)v);
    }
    __threadfence();
    __syncthreads();

    if (tid == 0) {
        unsigned old = atomicAdd(&g_cnt[blockIdx.x], 1u);
        s_last = (old == KSPLIT - 1) ? 1 : 0;
    }
    __syncthreads();

    if (s_last) {
        __threadfence();   // acquire: see all columns' g_acc updates
#pragma unroll
        for (int j = 0; j < NPT; j++) {
            int n = nbase + tid + j * TPB;
            long long v = (long long)__ldcg(&g_acc[n]);
            float s = (float)v * INVFIX;
            float e = ex2f(-s * 1.4426950408889634f);
            out[n] = 1.0f / (1.0f + e);
            g_acc[n] = 0ull;            // reset for next graph replay
        }
        if (tid == 0) g_cnt[blockIdx.x] = 0u;
    }
}

// ---------------------------------------------------------------------------
extern "C" void kernel_launch(void* const* d_in, const int* in_sizes, int n_in,
                              void* d_out, int out_size)
{
    const float* origins    = (const float*)d_in[0];
    const float* directions = (const float*)d_in[1];
    const float* embeddings = (const float*)d_in[2];
    const float* chol       = (const float*)d_in[3];
    const float* labels     = (const float*)d_in[4];
    const int*   idx        = (const int*)  d_in[5];
    float* out = (float*)d_out;

    fused_kernel<<<dim3(NBLK, KSPLIT), TPB>>>(origins, directions, embeddings,
                                              chol, labels, idx, out);
}

// round 9
// speedup vs baseline: 2.1159x; 1.0667x over previous
#include <cuda_runtime.h>
#include <cuda_bf16.h>

// Problem constants
#define NRAYS   8192
#define KSEL    4096
#define KSPLIT  64
#define CHUNK   (KSEL / KSPLIT)        // 64 gaussians per block
#define TPB     128
#define NPT     4                      // rays per thread
#define RPB     (TPB * NPT)            // 512 rays per block column
#define NBLK    (NRAYS / RPB)          // 16 columns -> grid (16,64) = 1024 blocks

// s = sqrt(0.5 * log2(e)) : folds exp(-0.5 q) -> 2^(-||W d||^2)
#define SCALE_S 0.8493281132464818f
#define FIXSCALE 1073741824.0          // 2^30 fixed-point scale (double)
#define INVFIX   (1.0f / 1073741824.0f)

// ---- scratch (__device__ globals; zero-initialized, self-resetting) -------
__device__ unsigned long long g_acc[NRAYS];   // fixed-point logit accumulators
__device__ unsigned           g_cnt[NBLK];    // per-column completion tickets

__device__ __forceinline__ float ex2f(float x) {
    float e;
    asm("ex2.approx.ftz.f32 %0, %1;" : "=f"(e) : "f"(x));
    return e;
}

// ---------------------------------------------------------------------------
// Single fused kernel: grid (NBLK, KSPLIT), 128 threads.
//  Phase 1 (threads 0..63): gather gaussian kbase+tid, W = s*L^{-1},
//    nc = -(W*mu), stage [W(10), nc(4), lab, pad] in shared.
//  Phase 2: scalar FMA mainloop, 4 rays/thread over 64 gaussians
//           (4 LDS.128 amortized over 60 FFMA issues per k per thread).
//  Phase 3: deterministic integer fixed-point atomic combine; the last
//    block of each ray column applies sigmoid, writes out, resets state.
// ---------------------------------------------------------------------------
__global__ void __launch_bounds__(TPB)
fused_kernel(const float* __restrict__ org,
             const float* __restrict__ dir,
             const float* __restrict__ emb,
             const float* __restrict__ chol,
             const float* __restrict__ labels,
             const int*   __restrict__ idx,
             float* __restrict__ out)
{
    __shared__ float4 sm[CHUNK * 4];   // 4 KB
    __shared__ int s_last;

    const int tid   = threadIdx.x;
    const int nbase = blockIdx.x * RPB;
    const int kbase = blockIdx.y * CHUNK;

    // ---- Phase 1: per-gaussian setup (threads 0..63) ----
    if (tid < CHUNK) {
        int m = __ldg(idx + kbase + tid);
        const float4* c4 = reinterpret_cast<const float4*>(chol) + (size_t)m * 4;
        float4 r0 = c4[0], r1 = c4[1], r2 = c4[2], r3 = c4[3];
        float L00 = r0.x;
        float L10 = r1.x, L11 = r1.y;
        float L20 = r2.x, L21 = r2.y, L22 = r2.z;
        float L30 = r3.x, L31 = r3.y, L32 = r3.z, L33 = r3.w;

        float i0 = 1.0f / L00, i1 = 1.0f / L11, i2 = 1.0f / L22, i3 = 1.0f / L33;

        float U00 = i0, U11 = i1, U22 = i2, U33 = i3;
        float U10 = -(L10 * U00) * i1;
        float U20 = -(L20 * U00 + L21 * U10) * i2;
        float U21 = -(L21 * U11) * i2;
        float U30 = -(L30 * U00 + L31 * U10 + L32 * U20) * i3;
        float U31 = -(L31 * U11 + L32 * U21) * i3;
        float U32 = -(L32 * U22) * i3;

        const float s = SCALE_S;
        U00 *= s; U10 *= s; U11 *= s; U20 *= s; U21 *= s; U22 *= s;
        U30 *= s; U31 *= s; U32 *= s; U33 *= s;

        float4 mu = reinterpret_cast<const float4*>(emb)[m];
        float nc0 = -(U00 * mu.x);
        float nc1 = -(U10 * mu.x + U11 * mu.y);
        float nc2 = -(U20 * mu.x + U21 * mu.y + U22 * mu.z);
        float nc3 = -(U30 * mu.x + U31 * mu.y + U32 * mu.z + U33 * mu.w);
        float lab = __ldg(labels + m);

        sm[tid * 4 + 0] = make_float4(U00, U10, U11, U20);
        sm[tid * 4 + 1] = make_float4(U21, U22, U30, U31);
        sm[tid * 4 + 2] = make_float4(U32, U33, nc0, nc1);
        sm[tid * 4 + 3] = make_float4(nc2, nc3, lab, 0.0f);
    }

    // ---- load rays (independent of shared) ----
    float p0[NPT], p1[NPT], p2[NPT], p3[NPT], acc[NPT];
    const float2* o2 = reinterpret_cast<const float2*>(org);
    const float2* d2 = reinterpret_cast<const float2*>(dir);
#pragma unroll
    for (int j = 0; j < NPT; j++) {
        int n = nbase + tid + j * TPB;
        float2 o = o2[n];
        float2 d = d2[n];
        p0[j] = o.x; p1[j] = o.y; p2[j] = d.x; p3[j] = d.y;
        acc[j] = 0.0f;
    }
    __syncthreads();

    // ---- Phase 2: scalar FMA mainloop ----
#pragma unroll 4
    for (int kk = 0; kk < CHUNK; kk++) {
        float4 f0 = sm[kk * 4 + 0];   // U00 U10 U11 U20
        float4 f1 = sm[kk * 4 + 1];   // U21 U22 U30 U31
        float4 f2 = sm[kk * 4 + 2];   // U32 U33 nc0 nc1
        float4 f3 = sm[kk * 4 + 3];   // nc2 nc3 lab pad
#pragma unroll
        for (int j = 0; j < NPT; j++) {
            float y0 = __fmaf_rn(f0.x, p0[j], f2.z);
            float y1 = __fmaf_rn(f0.y, p0[j], f2.w);
            y1 = __fmaf_rn(f0.z, p1[j], y1);
            float y2 = __fmaf_rn(f0.w, p0[j], f3.x);
            y2 = __fmaf_rn(f1.x, p1[j], y2);
            y2 = __fmaf_rn(f1.y, p2[j], y2);
            float y3 = __fmaf_rn(f1.z, p0[j], f3.y);
            y3 = __fmaf_rn(f1.w, p1[j], y3);
            y3 = __fmaf_rn(f2.x, p2[j], y3);
            y3 = __fmaf_rn(f2.y, p3[j], y3);
            float qn = -(y0 * y0);
            qn = __fmaf_rn(y1, -y1, qn);
            qn = __fmaf_rn(y2, -y2, qn);
            qn = __fmaf_rn(y3, -y3, qn);
            acc[j] = __fmaf_rn(f3.z, ex2f(qn), acc[j]);
        }
    }

    // ---- Phase 3: deterministic integer combine ----
#pragma unroll
    for (int j = 0; j < NPT; j++) {
        int n = nbase + tid + j * TPB;
        long long v = (long long)((double)acc[j] * FIXSCALE);  // order-free integer sum
        atomicAdd(&g_acc[n], (unsigned long long)v);
    }
    __threadfence();
    __syncthreads();

    if (tid == 0) {
        unsigned old = atomicAdd(&g_cnt[blockIdx.x], 1u);
        s_last = (old == KSPLIT - 1) ? 1 : 0;
    }
    __syncthreads();

    if (s_last) {
        __threadfence();   // acquire: see all columns' g_acc updates
#pragma unroll
        for (int j = 0; j < NPT; j++) {
            int n = nbase + tid + j * TPB;
            long long v = (long long)__ldcg(&g_acc[n]);
            float s = (float)v * INVFIX;
            float e = ex2f(-s * 1.4426950408889634f);
            out[n] = 1.0f / (1.0f + e);
            g_acc[n] = 0ull;            // reset for next graph replay
        }
        if (tid == 0) g_cnt[blockIdx.x] = 0u;
    }
}

// ---------------------------------------------------------------------------
extern "C" void kernel_launch(void* const* d_in, const int* in_sizes, int n_in,
                              void* d_out, int out_size)
{
    const float* origins    = (const float*)d_in[0];
    const float* directions = (const float*)d_in[1];
    const float* embeddings = (const float*)d_in[2];
    const float* chol       = (const float*)d_in[3];
    const float* labels     = (const float*)d_in[4];
    const int*   idx        = (const int*)  d_in[5];
    float* out = (float*)d_out;

    fused_kernel<<<dim3(NBLK, KSPLIT), TPB>>>(origins, directions, embeddings,
                                              chol, labels, idx, out);
}